// round 9
// baseline (speedup 1.0000x reference)
#include <cuda_runtime.h>
#include <cstdint>

// GraphReversePool: out[b, v] = x[b, v2c[v]]
//   x   : [BATCH, N_CLUSTERS] fp32   (d_in[0])
//   v2c : [VERTICES] int32           (d_in[1])
//   out : [BATCH, VERTICES] fp32
//
// R8: R5 macro-shape (grid=batch, 1 row/CTA, cp.async.bulk row staging,
// 2 CTAs/SM) -- proven best. Gather body unrolled to 4 independent quads
// per warp-iteration (4x LDG.128 idx -> 16x LDS -> 4x STG.128.cs) to close
// the latency-exposure gap (L1 pipe at 74%, target ~80%+).

#define BLOCK_THREADS 1024

__device__ __forceinline__ uint32_t smem_u32(const void* p) {
    return (uint32_t)__cvta_generic_to_shared(p);
}

__global__ __launch_bounds__(BLOCK_THREADS, 2)
void graph_reverse_pool_kernel(const float* __restrict__ x,
                               const int*   __restrict__ v2c,
                               float*       __restrict__ out,
                               int batch, int n_clusters, int n_vertices)
{
    extern __shared__ __align__(16) unsigned char smem_raw[];
    float* srow = reinterpret_cast<float*>(smem_raw);

    const int b = blockIdx.x;

    const int row_bytes = n_clusters * 4;
    const int mbar_off  = (row_bytes + 15) & ~15;
    uint64_t* mbar = reinterpret_cast<uint64_t*>(smem_raw + mbar_off);
    const uint32_t mbar_addr = smem_u32(mbar);

    const float* __restrict__ xrow = x + (size_t)b * n_clusters;

    const bool can_bulk = ((row_bytes & 15) == 0) &&
                          ((((uintptr_t)xrow) & 15) == 0);

    if (can_bulk) {
        if (threadIdx.x == 0) {
            asm volatile("mbarrier.init.shared.b64 [%0], 1;"
                         :: "r"(mbar_addr) : "memory");
            asm volatile("fence.proxy.async.shared::cta;" ::: "memory");
        }
        __syncthreads();
        if (threadIdx.x == 0) {
            asm volatile("mbarrier.arrive.expect_tx.shared.b64 _, [%0], %1;"
                         :: "r"(mbar_addr), "r"((uint32_t)row_bytes) : "memory");
            asm volatile("cp.async.bulk.shared::cta.global.mbarrier::complete_tx::bytes "
                         "[%0], [%1], %2, [%3];"
                         :: "r"(smem_u32(srow)), "l"(xrow),
                            "r"((uint32_t)row_bytes), "r"(mbar_addr)
                         : "memory");
        }
        uint32_t done = 0;
        while (!done) {
            asm volatile(
                "{\n\t.reg .pred p;\n\t"
                "mbarrier.try_wait.parity.acquire.cta.shared::cta.b64 p, [%1], 0, 0x989680;\n\t"
                "selp.b32 %0, 1, 0, p;\n\t}"
                : "=r"(done) : "r"(mbar_addr) : "memory");
        }
    } else {
        for (int i = threadIdx.x; i < n_clusters; i += BLOCK_THREADS)
            srow[i] = xrow[i];
        __syncthreads();
    }

    // ---- Gather: 4 independent quads per iteration ----
    const int4* __restrict__ v2c4 = reinterpret_cast<const int4*>(v2c);
    float4* __restrict__ o = reinterpret_cast<float4*>(out + (size_t)b * n_vertices);

    const int nv4 = n_vertices >> 2;           // 100000/4 = 25000, exact
    const int S = BLOCK_THREADS;

    int v = threadIdx.x;
    while (v + 3 * S < nv4) {
        const int4 c0 = v2c4[v];
        const int4 c1 = v2c4[v +     S];
        const int4 c2 = v2c4[v + 2 * S];
        const int4 c3 = v2c4[v + 3 * S];
        float4 a0, a1, a2, a3;
        a0.x = srow[c0.x]; a0.y = srow[c0.y]; a0.z = srow[c0.z]; a0.w = srow[c0.w];
        a1.x = srow[c1.x]; a1.y = srow[c1.y]; a1.z = srow[c1.z]; a1.w = srow[c1.w];
        a2.x = srow[c2.x]; a2.y = srow[c2.y]; a2.z = srow[c2.z]; a2.w = srow[c2.w];
        a3.x = srow[c3.x]; a3.y = srow[c3.y]; a3.z = srow[c3.z]; a3.w = srow[c3.w];
        __stcs(&o[v],         a0);
        __stcs(&o[v +     S], a1);
        __stcs(&o[v + 2 * S], a2);
        __stcs(&o[v + 3 * S], a3);
        v += 4 * S;
    }
    while (v < nv4) {
        const int4 c = v2c4[v];
        float4 a;
        a.x = srow[c.x]; a.y = srow[c.y]; a.z = srow[c.z]; a.w = srow[c.w];
        __stcs(&o[v], a);
        v += S;
    }
    // scalar vertex tail (dead for 100000, kept for safety)
    for (int t = (nv4 << 2) + threadIdx.x; t < n_vertices; t += BLOCK_THREADS) {
        out[(size_t)b * n_vertices + t] = srow[v2c[t]];
    }
}

extern "C" void kernel_launch(void* const* d_in, const int* in_sizes, int n_in,
                              void* d_out, int out_size)
{
    const float* x   = (const float*)d_in[0];
    const int*   v2c = (const int*)  d_in[1];
    float*       out = (float*)d_out;

    const int n_vertices = in_sizes[1];                  // 100000
    const int batch      = out_size / n_vertices;        // 1024
    const int n_clusters = in_sizes[0] / batch;          // 25000

    const int row_bytes  = n_clusters * (int)sizeof(float);      // 100000
    const int smem_bytes = ((row_bytes + 15) & ~15) + 16;        // row + mbarrier

    static bool attr_set = false;
    if (!attr_set) {
        cudaFuncSetAttribute(graph_reverse_pool_kernel,
                             cudaFuncAttributeMaxDynamicSharedMemorySize,
                             smem_bytes);
        attr_set = true;
    }

    graph_reverse_pool_kernel<<<batch, BLOCK_THREADS, smem_bytes>>>(
        x, v2c, out, batch, n_clusters, n_vertices);
}